// round 7
// baseline (speedup 1.0000x reference)
#include <cuda_runtime.h>

#define H 27
#define G4 (4*H)          // 108
#define T_STEPS 78
#define LAYERS 3
#define WARPS_PER_BLOCK 8
#define THREADS 256
#define EPW 8             // batch elements per warp
#define PAIRS 4           // EPW/2 f32x2 pairs
#define WTILE 729         // 27*27

typedef unsigned long long ull;

__device__ __forceinline__ ull dup2(float v) {
    ull r; asm("mov.b64 %0, {%1, %1};" : "=l"(r) : "f"(v)); return r;
}
__device__ __forceinline__ ull pack2(float lo, float hi) {
    ull r; asm("mov.b64 %0, {%1, %2};" : "=l"(r) : "f"(lo), "f"(hi)); return r;
}
__device__ __forceinline__ void unpack2(ull v, float& lo, float& hi) {
    asm("mov.b64 {%0, %1}, %2;" : "=f"(lo), "=f"(hi) : "l"(v));
}
__device__ __forceinline__ ull fma2(ull a, ull b, ull c) {
    ull d; asm("fma.rn.f32x2 %0, %1, %2, %3;" : "=l"(d) : "l"(a), "l"(b), "l"(c)); return d;
}

__device__ __forceinline__ float fast_sigmoid(float z) {
    return __fdividef(1.0f, 1.0f + __expf(-z));
}
__device__ __forceinline__ float fast_tanh(float z) {
    return 1.0f - 2.0f * __fdividef(1.0f, __expf(2.0f * z) + 1.0f);
}

// ---- shared memory layout (bytes) ----
// WX   : [3][729] float4        0      .. 34992
// WH   : [3][729] float4        34992  .. 69984
// BIAS : [3][27]  float4        69984  .. 71280
// WLs  : [729]    float         71280  .. 74196  (pad to 74208)
// BUFS : [8 warps][5 bufs: A,B,H0,H1,H2][27][2] ulonglong2
#define SM_WX    0
#define SM_WH    34992
#define SM_BIAS  69984
#define SM_WLS   71280
#define SM_BUFS  74208
#define BUF_U2   54              // 54 ulonglong2 = 864 B per buffer
#define BUF_BYTES 864
#define BUFS_PER_WARP 5
#define SMEM_TOTAL (SM_BUFS + WARPS_PER_BLOCK * BUFS_PER_WARP * BUF_BYTES)   // 108768

extern __shared__ char smem_raw[];

__global__ void __launch_bounds__(THREADS, 2)
lstm3_fused_kernel(const float* __restrict__ x,
                   const float* __restrict__ h0,
                   const float* __restrict__ c0,
                   const float* __restrict__ Wih,
                   const float* __restrict__ Whh,
                   const float* __restrict__ bih,
                   const float* __restrict__ bhh,
                   const float* __restrict__ Wl,
                   const float* __restrict__ bl,
                   float* __restrict__ out,
                   int B)
{
    float4* WX   = (float4*)(smem_raw + SM_WX);
    float4* WH   = (float4*)(smem_raw + SM_WH);
    float4* BIAS = (float4*)(smem_raw + SM_BIAS);
    float*  WLs  = (float*)(smem_raw + SM_WLS);

    const int tid = threadIdx.x;

    // ---- stage packed weights into shared ----
    for (int idx = tid; idx < LAYERS * 2 * WTILE; idx += THREADS) {
        int l   = idx / (2 * WTILE);
        int rem = idx % (2 * WTILE);
        int m   = rem / WTILE;       // 0 = Wih, 1 = Whh
        int r   = rem % WTILE;
        int k   = r / H;
        int j   = r % H;
        const float* W = ((m == 0) ? Wih : Whh) + (size_t)l * G4 * H;
        float4 v;
        v.x = W[(0 * H + j) * H + k];
        v.y = W[(1 * H + j) * H + k];
        v.z = W[(2 * H + j) * H + k];
        v.w = W[(3 * H + j) * H + k];
        ((m == 0) ? WX : WH)[l * WTILE + k * H + j] = v;
    }
    for (int idx = tid; idx < LAYERS * H; idx += THREADS) {
        int l = idx / H, j = idx % H;
        const float* b1 = bih + l * G4;
        const float* b2 = bhh + l * G4;
        float4 v;
        v.x = b1[0 * H + j] + b2[0 * H + j];
        v.y = b1[1 * H + j] + b2[1 * H + j];
        v.z = b1[2 * H + j] + b2[2 * H + j];
        v.w = b1[3 * H + j] + b2[3 * H + j];
        BIAS[l * H + j] = v;
    }
    for (int idx = tid; idx < WTILE; idx += THREADS) {
        int k = idx / H, j = idx % H;
        WLs[k * H + j] = Wl[j * H + k];
    }
    __syncthreads();

    const int warp = tid >> 5;
    const int lane = tid & 31;
    const int b0 = (blockIdx.x * WARPS_PER_BLOCK + warp) * EPW;
    if (b0 >= B) return;

    const int  j     = (lane < H) ? lane : (H - 1);
    const bool store = (lane < H);

    ulonglong2* bufA  = (ulonglong2*)(smem_raw + SM_BUFS + warp * BUFS_PER_WARP * BUF_BYTES);
    ulonglong2* bufB  = bufA + BUF_U2;
    ulonglong2* bufH0 = bufB + BUF_U2;   // bufH[l] = bufH0 + l*BUF_U2

    const float blj = bl[j];

    // ---- init: h state lives in SMEM (bufH[l]); c state in registers ----
    float cr[LAYERS][EPW];
    #pragma unroll
    for (int l = 0; l < LAYERS; l++) {
        if (store) {
            ull p0 = pack2(h0[((size_t)l * B + (b0 + 0)) * H + j],
                           h0[((size_t)l * B + (b0 + 1)) * H + j]);
            ull p1 = pack2(h0[((size_t)l * B + (b0 + 2)) * H + j],
                           h0[((size_t)l * B + (b0 + 3)) * H + j]);
            ull p2 = pack2(h0[((size_t)l * B + (b0 + 4)) * H + j],
                           h0[((size_t)l * B + (b0 + 5)) * H + j]);
            ull p3 = pack2(h0[((size_t)l * B + (b0 + 6)) * H + j],
                           h0[((size_t)l * B + (b0 + 7)) * H + j]);
            (bufH0 + l * BUF_U2)[j * 2 + 0] = make_ulonglong2(p0, p1);
            (bufH0 + l * BUF_U2)[j * 2 + 1] = make_ulonglong2(p2, p3);
        }
        #pragma unroll
        for (int e = 0; e < EPW; e++)
            cr[l][e] = c0[((size_t)l * B + (b0 + e)) * H + j];
    }

    const float* xrow = x   + (size_t)b0 * T_STEPS * H;
    float*       orow = out + (size_t)b0 * T_STEPS * H;

    // prefetch x for t=0, packed
    ull xp[PAIRS];
    #pragma unroll
    for (int p = 0; p < PAIRS; p++)
        xp[p] = pack2(xrow[(size_t)(2*p    ) * T_STEPS * H + j],
                      xrow[(size_t)(2*p + 1) * T_STEPS * H + j]);

    for (int t = 0; t < T_STEPS; t++) {
        // stage x into bufA (layer-0 input); also fences prev-t final-linear reads
        if (store) {
            bufA[j * 2 + 0] = make_ulonglong2(xp[0], xp[1]);
            bufA[j * 2 + 1] = make_ulonglong2(xp[2], xp[3]);
        }
        if (t + 1 < T_STEPS) {
            #pragma unroll
            for (int p = 0; p < PAIRS; p++)
                xp[p] = pack2(xrow[(size_t)(2*p    ) * T_STEPS * H + (t+1) * H + j],
                              xrow[(size_t)(2*p + 1) * T_STEPS * H + (t+1) * H + j]);
        }
        __syncwarp();

        #pragma unroll
        for (int l = 0; l < LAYERS; l++) {
            ulonglong2* inb   = (l == 1) ? bufB : bufA;
            ulonglong2* outb  = (l == 1) ? bufA : bufB;
            ulonglong2* bufHl = bufH0 + l * BUF_U2;
            const float4* wx = WX + l * WTILE;
            const float4* wh = WH + l * WTILE;

            float4 bv = BIAS[l * H + j];
            ull acc[4][PAIRS];
            {
                ull bi = dup2(bv.x), bf = dup2(bv.y), bg = dup2(bv.z), bo = dup2(bv.w);
                #pragma unroll
                for (int p = 0; p < PAIRS; p++) {
                    acc[0][p] = bi; acc[1][p] = bf; acc[2][p] = bg; acc[3][p] = bo;
                }
            }

            #pragma unroll 9
            for (int k = 0; k < H; k++) {
                float4 a = wx[k * H + j];
                float4 d = wh[k * H + j];
                ulonglong2 x01 = inb[k * 2 + 0];
                ulonglong2 x23 = inb[k * 2 + 1];
                ulonglong2 h01 = bufHl[k * 2 + 0];
                ulonglong2 h23 = bufHl[k * 2 + 1];
                ull xk[PAIRS] = { x01.x, x01.y, x23.x, x23.y };
                ull hk[PAIRS] = { h01.x, h01.y, h23.x, h23.y };
                ull w;
                w = dup2(a.x);
                #pragma unroll
                for (int p = 0; p < PAIRS; p++) acc[0][p] = fma2(w, xk[p], acc[0][p]);
                w = dup2(a.y);
                #pragma unroll
                for (int p = 0; p < PAIRS; p++) acc[1][p] = fma2(w, xk[p], acc[1][p]);
                w = dup2(a.z);
                #pragma unroll
                for (int p = 0; p < PAIRS; p++) acc[2][p] = fma2(w, xk[p], acc[2][p]);
                w = dup2(a.w);
                #pragma unroll
                for (int p = 0; p < PAIRS; p++) acc[3][p] = fma2(w, xk[p], acc[3][p]);
                w = dup2(d.x);
                #pragma unroll
                for (int p = 0; p < PAIRS; p++) acc[0][p] = fma2(w, hk[p], acc[0][p]);
                w = dup2(d.y);
                #pragma unroll
                for (int p = 0; p < PAIRS; p++) acc[1][p] = fma2(w, hk[p], acc[1][p]);
                w = dup2(d.z);
                #pragma unroll
                for (int p = 0; p < PAIRS; p++) acc[2][p] = fma2(w, hk[p], acc[2][p]);
                w = dup2(d.w);
                #pragma unroll
                for (int p = 0; p < PAIRS; p++) acc[3][p] = fma2(w, hk[p], acc[3][p]);
            }
            __syncwarp();   // all lanes done reading inb / bufHl

            // gates + state update; write h to bufHl (next t) and outb (next layer)
            #pragma unroll
            for (int p = 0; p < PAIRS; p++) {
                float ilo, ihi, flo, fhi, glo, ghi, olo, ohi;
                unpack2(acc[0][p], ilo, ihi);
                unpack2(acc[1][p], flo, fhi);
                unpack2(acc[2][p], glo, ghi);
                unpack2(acc[3][p], olo, ohi);
                ilo = fast_sigmoid(ilo); ihi = fast_sigmoid(ihi);
                flo = fast_sigmoid(flo); fhi = fast_sigmoid(fhi);
                glo = fast_tanh(glo);    ghi = fast_tanh(ghi);
                olo = fast_sigmoid(olo); ohi = fast_sigmoid(ohi);
                float clo = fmaf(flo, cr[l][2*p    ], ilo * glo);
                float chi = fmaf(fhi, cr[l][2*p + 1], ihi * ghi);
                cr[l][2*p    ] = clo;
                cr[l][2*p + 1] = chi;
                acc[0][p] = pack2(olo * fast_tanh(clo), ohi * fast_tanh(chi));
            }
            if (store) {
                ulonglong2 v0 = make_ulonglong2(acc[0][0], acc[0][1]);
                ulonglong2 v1 = make_ulonglong2(acc[0][2], acc[0][3]);
                bufHl[j * 2 + 0] = v0;
                bufHl[j * 2 + 1] = v1;
                outb[j * 2 + 0] = v0;
                outb[j * 2 + 1] = v1;
            }
            __syncwarp();
        }

        // ---- final linear: reads bufB (layer-2 output) ----
        {
            ull accf[PAIRS];
            ull bb = dup2(blj);
            #pragma unroll
            for (int p = 0; p < PAIRS; p++) accf[p] = bb;

            #pragma unroll 9
            for (int k = 0; k < H; k++) {
                ull w = dup2(WLs[k * H + j]);
                ulonglong2 f01 = bufB[k * 2 + 0];
                ulonglong2 f23 = bufB[k * 2 + 1];
                accf[0] = fma2(w, f01.x, accf[0]);
                accf[1] = fma2(w, f01.y, accf[1]);
                accf[2] = fma2(w, f23.x, accf[2]);
                accf[3] = fma2(w, f23.y, accf[3]);
            }
            if (store) {
                #pragma unroll
                for (int p = 0; p < PAIRS; p++) {
                    float lo, hi;
                    unpack2(accf[p], lo, hi);
                    orow[(size_t)(2*p    ) * T_STEPS * H + t * H + lane] = lo;
                    orow[(size_t)(2*p + 1) * T_STEPS * H + t * H + lane] = hi;
                }
            }
        }
    }
}

extern "C" void kernel_launch(void* const* d_in, const int* in_sizes, int n_in,
                              void* d_out, int out_size)
{
    const float* x   = (const float*)d_in[0];
    const float* h0  = (const float*)d_in[1];
    const float* c0  = (const float*)d_in[2];
    const float* Wih = (const float*)d_in[3];
    const float* Whh = (const float*)d_in[4];
    const float* bih = (const float*)d_in[5];
    const float* bhh = (const float*)d_in[6];
    const float* Wl  = (const float*)d_in[7];
    const float* bl  = (const float*)d_in[8];
    float* out = (float*)d_out;

    const int B = in_sizes[0] / (T_STEPS * H);   // 32768

    static bool attr_set = false;
    if (!attr_set) {
        cudaFuncSetAttribute(lstm3_fused_kernel,
                             cudaFuncAttributeMaxDynamicSharedMemorySize, SMEM_TOTAL);
        attr_set = true;
    }

    const int per_block = WARPS_PER_BLOCK * EPW;                // 64
    const int grid = (B + per_block - 1) / per_block;           // 512
    lstm3_fused_kernel<<<grid, THREADS, SMEM_TOTAL>>>(
        x, h0, c0, Wih, Whh, bih, bhh, Wl, bl, out, B);
}

// round 8
// speedup vs baseline: 1.0021x; 1.0021x over previous
#include <cuda_runtime.h>

#define H 27
#define G4 (4*H)          // 108
#define T_STEPS 78
#define LAYERS 3
#define WARPS_PER_BLOCK 8
#define THREADS 256
#define EPW 8             // batch elements per warp
#define PAIRS 4           // EPW/2 f32x2 pairs
#define WTILE 729         // 27*27

typedef unsigned long long ull;

__device__ __forceinline__ ull dup2(float v) {
    ull r; asm("mov.b64 %0, {%1, %1};" : "=l"(r) : "f"(v)); return r;
}
__device__ __forceinline__ ull pack2(float lo, float hi) {
    ull r; asm("mov.b64 %0, {%1, %2};" : "=l"(r) : "f"(lo), "f"(hi)); return r;
}
__device__ __forceinline__ void unpack2(ull v, float& lo, float& hi) {
    asm("mov.b64 {%0, %1}, %2;" : "=f"(lo), "=f"(hi) : "l"(v));
}
__device__ __forceinline__ ull fma2(ull a, ull b, ull c) {
    ull d; asm("fma.rn.f32x2 %0, %1, %2, %3;" : "=l"(d) : "l"(a), "l"(b), "l"(c)); return d;
}

__device__ __forceinline__ float fast_sigmoid(float z) {
    return __fdividef(1.0f, 1.0f + __expf(-z));
}
__device__ __forceinline__ float fast_tanh(float z) {
    return 1.0f - 2.0f * __fdividef(1.0f, __expf(2.0f * z) + 1.0f);
}

// ---- shared memory layout (bytes) ----
// WX   : [3][729] float4        0      .. 34992
// WH   : [3][729] float4        34992  .. 69984
// BIAS : [3][27]  float4        69984  .. 71280
// WLs  : [729]    float         71280  .. 74196  (pad to 74208)
// BUFS : [8 warps][5 bufs: A,B,H0,H1,H2][27][2] ulonglong2
#define SM_WX    0
#define SM_WH    34992
#define SM_BIAS  69984
#define SM_WLS   71280
#define SM_BUFS  74208
#define BUF_U2   54              // 54 ulonglong2 = 864 B per buffer
#define BUF_BYTES 864
#define BUFS_PER_WARP 5
#define SMEM_TOTAL (SM_BUFS + WARPS_PER_BLOCK * BUFS_PER_WARP * BUF_BYTES)   // 108768

extern __shared__ char smem_raw[];

__global__ void __launch_bounds__(THREADS, 2)
lstm3_fused_kernel(const float* __restrict__ x,
                   const float* __restrict__ h0,
                   const float* __restrict__ c0,
                   const float* __restrict__ Wih,
                   const float* __restrict__ Whh,
                   const float* __restrict__ bih,
                   const float* __restrict__ bhh,
                   const float* __restrict__ Wl,
                   const float* __restrict__ bl,
                   float* __restrict__ out,
                   int B)
{
    float4* WX   = (float4*)(smem_raw + SM_WX);
    float4* WH   = (float4*)(smem_raw + SM_WH);
    float4* BIAS = (float4*)(smem_raw + SM_BIAS);
    float*  WLs  = (float*)(smem_raw + SM_WLS);

    const int tid = threadIdx.x;

    // ---- stage packed weights into shared ----
    for (int idx = tid; idx < LAYERS * 2 * WTILE; idx += THREADS) {
        int l   = idx / (2 * WTILE);
        int rem = idx % (2 * WTILE);
        int m   = rem / WTILE;       // 0 = Wih, 1 = Whh
        int r   = rem % WTILE;
        int k   = r / H;
        int j   = r % H;
        const float* W = ((m == 0) ? Wih : Whh) + (size_t)l * G4 * H;
        float4 v;
        v.x = W[(0 * H + j) * H + k];
        v.y = W[(1 * H + j) * H + k];
        v.z = W[(2 * H + j) * H + k];
        v.w = W[(3 * H + j) * H + k];
        ((m == 0) ? WX : WH)[l * WTILE + k * H + j] = v;
    }
    for (int idx = tid; idx < LAYERS * H; idx += THREADS) {
        int l = idx / H, j = idx % H;
        const float* b1 = bih + l * G4;
        const float* b2 = bhh + l * G4;
        float4 v;
        v.x = b1[0 * H + j] + b2[0 * H + j];
        v.y = b1[1 * H + j] + b2[1 * H + j];
        v.z = b1[2 * H + j] + b2[2 * H + j];
        v.w = b1[3 * H + j] + b2[3 * H + j];
        BIAS[l * H + j] = v;
    }
    for (int idx = tid; idx < WTILE; idx += THREADS) {
        int k = idx / H, j = idx % H;
        WLs[k * H + j] = Wl[j * H + k];
    }
    __syncthreads();

    const int warp = tid >> 5;
    const int lane = tid & 31;
    const int b0 = (blockIdx.x * WARPS_PER_BLOCK + warp) * EPW;
    if (b0 >= B) return;

    const int  j     = (lane < H) ? lane : (H - 1);
    const bool store = (lane < H);

    ulonglong2* bufA  = (ulonglong2*)(smem_raw + SM_BUFS + warp * BUFS_PER_WARP * BUF_BYTES);
    ulonglong2* bufB  = bufA + BUF_U2;
    ulonglong2* bufH0 = bufB + BUF_U2;   // bufH[l] = bufH0 + l*BUF_U2

    const float blj = bl[j];

    // ---- init: h state lives in SMEM (bufH[l]); c state in registers ----
    float cr[LAYERS][EPW];
    #pragma unroll
    for (int l = 0; l < LAYERS; l++) {
        if (store) {
            ull p0 = pack2(h0[((size_t)l * B + (b0 + 0)) * H + j],
                           h0[((size_t)l * B + (b0 + 1)) * H + j]);
            ull p1 = pack2(h0[((size_t)l * B + (b0 + 2)) * H + j],
                           h0[((size_t)l * B + (b0 + 3)) * H + j]);
            ull p2 = pack2(h0[((size_t)l * B + (b0 + 4)) * H + j],
                           h0[((size_t)l * B + (b0 + 5)) * H + j]);
            ull p3 = pack2(h0[((size_t)l * B + (b0 + 6)) * H + j],
                           h0[((size_t)l * B + (b0 + 7)) * H + j]);
            (bufH0 + l * BUF_U2)[j * 2 + 0] = make_ulonglong2(p0, p1);
            (bufH0 + l * BUF_U2)[j * 2 + 1] = make_ulonglong2(p2, p3);
        }
        #pragma unroll
        for (int e = 0; e < EPW; e++)
            cr[l][e] = c0[((size_t)l * B + (b0 + e)) * H + j];
    }

    const float* xrow = x   + (size_t)b0 * T_STEPS * H;
    float*       orow = out + (size_t)b0 * T_STEPS * H;

    // prefetch x for t=0, packed
    ull xp[PAIRS];
    #pragma unroll
    for (int p = 0; p < PAIRS; p++)
        xp[p] = pack2(xrow[(size_t)(2*p    ) * T_STEPS * H + j],
                      xrow[(size_t)(2*p + 1) * T_STEPS * H + j]);

    for (int t = 0; t < T_STEPS; t++) {
        // stage x into bufA (layer-0 input); also fences prev-t final-linear reads
        if (store) {
            bufA[j * 2 + 0] = make_ulonglong2(xp[0], xp[1]);
            bufA[j * 2 + 1] = make_ulonglong2(xp[2], xp[3]);
        }
        if (t + 1 < T_STEPS) {
            #pragma unroll
            for (int p = 0; p < PAIRS; p++)
                xp[p] = pack2(xrow[(size_t)(2*p    ) * T_STEPS * H + (t+1) * H + j],
                              xrow[(size_t)(2*p + 1) * T_STEPS * H + (t+1) * H + j]);
        }
        __syncwarp();

        #pragma unroll
        for (int l = 0; l < LAYERS; l++) {
            ulonglong2* inb   = (l == 1) ? bufB : bufA;
            ulonglong2* outb  = (l == 1) ? bufA : bufB;
            ulonglong2* bufHl = bufH0 + l * BUF_U2;
            const float4* wx = WX + l * WTILE;
            const float4* wh = WH + l * WTILE;

            float4 bv = BIAS[l * H + j];
            ull acc[4][PAIRS];
            {
                ull bi = dup2(bv.x), bf = dup2(bv.y), bg = dup2(bv.z), bo = dup2(bv.w);
                #pragma unroll
                for (int p = 0; p < PAIRS; p++) {
                    acc[0][p] = bi; acc[1][p] = bf; acc[2][p] = bg; acc[3][p] = bo;
                }
            }

            #pragma unroll 9
            for (int k = 0; k < H; k++) {
                float4 a = wx[k * H + j];
                float4 d = wh[k * H + j];
                ulonglong2 x01 = inb[k * 2 + 0];
                ulonglong2 x23 = inb[k * 2 + 1];
                ulonglong2 h01 = bufHl[k * 2 + 0];
                ulonglong2 h23 = bufHl[k * 2 + 1];
                ull xk[PAIRS] = { x01.x, x01.y, x23.x, x23.y };
                ull hk[PAIRS] = { h01.x, h01.y, h23.x, h23.y };
                ull w;
                w = dup2(a.x);
                #pragma unroll
                for (int p = 0; p < PAIRS; p++) acc[0][p] = fma2(w, xk[p], acc[0][p]);
                w = dup2(a.y);
                #pragma unroll
                for (int p = 0; p < PAIRS; p++) acc[1][p] = fma2(w, xk[p], acc[1][p]);
                w = dup2(a.z);
                #pragma unroll
                for (int p = 0; p < PAIRS; p++) acc[2][p] = fma2(w, xk[p], acc[2][p]);
                w = dup2(a.w);
                #pragma unroll
                for (int p = 0; p < PAIRS; p++) acc[3][p] = fma2(w, xk[p], acc[3][p]);
                w = dup2(d.x);
                #pragma unroll
                for (int p = 0; p < PAIRS; p++) acc[0][p] = fma2(w, hk[p], acc[0][p]);
                w = dup2(d.y);
                #pragma unroll
                for (int p = 0; p < PAIRS; p++) acc[1][p] = fma2(w, hk[p], acc[1][p]);
                w = dup2(d.z);
                #pragma unroll
                for (int p = 0; p < PAIRS; p++) acc[2][p] = fma2(w, hk[p], acc[2][p]);
                w = dup2(d.w);
                #pragma unroll
                for (int p = 0; p < PAIRS; p++) acc[3][p] = fma2(w, hk[p], acc[3][p]);
            }
            __syncwarp();   // all lanes done reading inb / bufHl

            // gates + state update; write h to bufHl (next t) and outb (next layer)
            #pragma unroll
            for (int p = 0; p < PAIRS; p++) {
                float ilo, ihi, flo, fhi, glo, ghi, olo, ohi;
                unpack2(acc[0][p], ilo, ihi);
                unpack2(acc[1][p], flo, fhi);
                unpack2(acc[2][p], glo, ghi);
                unpack2(acc[3][p], olo, ohi);
                ilo = fast_sigmoid(ilo); ihi = fast_sigmoid(ihi);
                flo = fast_sigmoid(flo); fhi = fast_sigmoid(fhi);
                glo = fast_tanh(glo);    ghi = fast_tanh(ghi);
                olo = fast_sigmoid(olo); ohi = fast_sigmoid(ohi);
                float clo = fmaf(flo, cr[l][2*p    ], ilo * glo);
                float chi = fmaf(fhi, cr[l][2*p + 1], ihi * ghi);
                cr[l][2*p    ] = clo;
                cr[l][2*p + 1] = chi;
                acc[0][p] = pack2(olo * fast_tanh(clo), ohi * fast_tanh(chi));
            }
            if (store) {
                ulonglong2 v0 = make_ulonglong2(acc[0][0], acc[0][1]);
                ulonglong2 v1 = make_ulonglong2(acc[0][2], acc[0][3]);
                bufHl[j * 2 + 0] = v0;
                bufHl[j * 2 + 1] = v1;
                outb[j * 2 + 0] = v0;
                outb[j * 2 + 1] = v1;
            }
            __syncwarp();
        }

        // ---- final linear: reads bufB (layer-2 output) ----
        {
            ull accf[PAIRS];
            ull bb = dup2(blj);
            #pragma unroll
            for (int p = 0; p < PAIRS; p++) accf[p] = bb;

            #pragma unroll 9
            for (int k = 0; k < H; k++) {
                ull w = dup2(WLs[k * H + j]);
                ulonglong2 f01 = bufB[k * 2 + 0];
                ulonglong2 f23 = bufB[k * 2 + 1];
                accf[0] = fma2(w, f01.x, accf[0]);
                accf[1] = fma2(w, f01.y, accf[1]);
                accf[2] = fma2(w, f23.x, accf[2]);
                accf[3] = fma2(w, f23.y, accf[3]);
            }
            if (store) {
                #pragma unroll
                for (int p = 0; p < PAIRS; p++) {
                    float lo, hi;
                    unpack2(accf[p], lo, hi);
                    orow[(size_t)(2*p    ) * T_STEPS * H + t * H + lane] = lo;
                    orow[(size_t)(2*p + 1) * T_STEPS * H + t * H + lane] = hi;
                }
            }
        }
    }
}

extern "C" void kernel_launch(void* const* d_in, const int* in_sizes, int n_in,
                              void* d_out, int out_size)
{
    const float* x   = (const float*)d_in[0];
    const float* h0  = (const float*)d_in[1];
    const float* c0  = (const float*)d_in[2];
    const float* Wih = (const float*)d_in[3];
    const float* Whh = (const float*)d_in[4];
    const float* bih = (const float*)d_in[5];
    const float* bhh = (const float*)d_in[6];
    const float* Wl  = (const float*)d_in[7];
    const float* bl  = (const float*)d_in[8];
    float* out = (float*)d_out;

    const int B = in_sizes[0] / (T_STEPS * H);   // 32768

    static bool attr_set = false;
    if (!attr_set) {
        cudaFuncSetAttribute(lstm3_fused_kernel,
                             cudaFuncAttributeMaxDynamicSharedMemorySize, SMEM_TOTAL);
        attr_set = true;
    }

    const int per_block = WARPS_PER_BLOCK * EPW;                // 64
    const int grid = (B + per_block - 1) / per_block;           // 512
    lstm3_fused_kernel<<<grid, THREADS, SMEM_TOTAL>>>(
        x, h0, c0, Wih, Whh, bih, bhh, Wl, bl, out, B);
}